// round 11
// baseline (speedup 1.0000x reference)
#include <cuda_runtime.h>
#include <cstdint>

#define IMG 128
#define BR  512
#define NSTROKES 1024
#define LSTROKES 256

// Scratch (device-global; no mallocs allowed).
__device__ uint32_t g_mask[2 * (BR * BR / 32)];   // fine brush>0 mask (fallback)
__device__ uint32_t g_coarse[512];                // 1 bit per fine word == all-ones
__device__ int      g_blockfull[64];              // per-prep-block "all ones" flag
// Packed SoA stroke params in DECK-MAJOR PERMUTED order:
//   stroke m (0..255 within batch) stored at pidx = (m&3)*64 + (63 - m/4)
__device__ float4 g_matA[NSTROKES];               // w00,w01,w02,w10
__device__ float4 g_matB[NSTROKES];               // w11,w12,bidx,0
__device__ float4 g_col[NSTROKES];                // cr,cg,cb,0

__device__ __forceinline__ int deck_pidx(int m) { // m = stroke index within batch
    return (m & 3) * 64 + (63 - (m >> 2));
}

// ---------------------------------------------------------------------------
// Kernel 1 (fused): blocks [0,64) build fine mask + coarse summary + block
// all-ones flag; blocks [64,96) compute stroke warp matrices (fp64 sin/cos
// spread over 32 SMs) and store them deck-major permuted.
// ---------------------------------------------------------------------------
__global__ void prep_and_mask_kernel(const float* __restrict__ params,
                                     const float* __restrict__ brushes) {
    const int bid = blockIdx.x;
    const int t = threadIdx.x;

    if (bid < 64) {
        __shared__ uint32_t s_f[8];
        const int word = bid * 256 + t;                 // 0 .. 16383
        const float4* src = (const float4*)brushes + word * 8;
        uint32_t m = 0;
        #pragma unroll
        for (int j = 0; j < 8; ++j) {
            float4 v = src[j];
            m |= ((v.x > 0.0f) ? 1u : 0u) << (4 * j + 0);
            m |= ((v.y > 0.0f) ? 1u : 0u) << (4 * j + 1);
            m |= ((v.z > 0.0f) ? 1u : 0u) << (4 * j + 2);
            m |= ((v.w > 0.0f) ? 1u : 0u) << (4 * j + 3);
        }
        g_mask[word] = m;
        unsigned full = __ballot_sync(0xFFFFFFFFu, m == 0xFFFFFFFFu);
        if ((t & 31) == 0) { g_coarse[word >> 5] = full; s_f[t >> 5] = full; }
        __syncthreads();
        if (t == 0) {
            bool all = true;
            #pragma unroll
            for (int i = 0; i < 8; ++i) all &= (s_f[i] == 0xFFFFFFFFu);
            g_blockfull[bid] = all ? 1 : 0;
        }
    } else {
        if (t >= 32) return;
        const int n = (bid - 64) * 32 + t;              // 0 .. 1023
        const float* p = params + n * 8;
        float x0 = p[0], y0 = p[1], w = p[2], h = p[3], th = p[4];

        // JAX: sin(fl32(pi)*theta), f32 product; correctly-rounded double
        // sin/cos keeps binary-alpha decisions bit-stable vs reference.
        float prod = 3.14159274101257324219f * th;
        float s = (float)sin((double)prod);
        float c = (float)cos((double)prod);

        float tx = 1.0f - 2.0f * x0;
        float ty = 1.0f - 2.0f * y0;
        const float w00 = c / w;
        const float w01 = s / w;
        const float w02 = (tx * c) / w + (ty * s) / w;
        const float w10 = -(s / h);
        const float w11 = c / h;
        const float w12 = (ty * c) / h - (tx * s) / h;

        const int b = n >> 8;                            // batch
        const int m = n & 255;                           // stroke within batch
        const int pidx = b * 256 + deck_pidx(m);
        g_matA[pidx] = make_float4(w00, w01, w02, w10);
        g_matB[pidx] = make_float4(w11, w12, (h > w) ? 0.0f : 1.0f, 0.0f);
        g_col[pidx]  = make_float4(p[5], p[6], p[7], 0.0f);
    }
}

// ---------------------------------------------------------------------------
// Render helpers (EXACT formulas — must match reference bit-for-bit).
// ---------------------------------------------------------------------------
__device__ __forceinline__ bool alpha_slow(int brush, float gx, float gy) {
    float x = ((gx + 1.0f) * 512.0f - 1.0f) * 0.5f;
    float y = ((gy + 1.0f) * 512.0f - 1.0f) * 0.5f;
    int ix = __float2int_rn(x);
    int iy = __float2int_rn(y);
    if ((unsigned)ix >= 512u || (unsigned)iy >= 512u) return false;
    int wi = (brush << 13) + (iy << 4) + (ix >> 5);
    if ((__ldg(g_coarse + (wi >> 5)) >> (wi & 31)) & 1u) return true;
    return (__ldg(g_mask + wi) >> (ix & 31)) & 1u;
}

__device__ __forceinline__ bool valid_fast(float bxn, float byn,
                                           float w00, float w01, float w02,
                                           float w10, float w11, float w12) {
    const float gx = fmaf(bxn, w00, fmaf(byn, w01, w02));
    const float gy = fmaf(bxn, w10, fmaf(byn, w11, w12));
    const float x = ((gx + 1.0f) * 512.0f - 1.0f) * 0.5f;
    const float y = ((gy + 1.0f) * 512.0f - 1.0f) * 0.5f;
    const int ix = __float2int_rn(x);
    const int iy = __float2int_rn(y);
    return ((unsigned)ix < 512u) & ((unsigned)iy < 512u);
}

__device__ __forceinline__ float tap(const float* __restrict__ im, int ix, int iy) {
    bool valid = ((unsigned)ix < 512u) && ((unsigned)iy < 512u);
    int cx = min(max(ix, 0), 511);
    int cy = min(max(iy, 0), 511);
    float v = __ldg(im + cy * 512 + cx);
    return valid ? v : 0.0f;
}

__device__ __forceinline__ float bgrid(int i) {     // exact base-grid coord
    return (2.0f * (float)i + 1.0f) * (1.0f / 128.0f) - 1.0f;
}

// ---------------------------------------------------------------------------
// Render: 2048 blocks x 128 threads = 1 (batch,tile) per block; warp k owns
// strokes l ≡ k (mod 4) descending, stored contiguously (coalesced LDG.128).
// No block barrier until the finale; allones flag computed per-warp.
// ---------------------------------------------------------------------------
__global__ __launch_bounds__(128, 12)
void render_kernel(const float* __restrict__ brushes, float* __restrict__ out) {
    __shared__ int s_win[4][32];

    const int t = threadIdx.x;
    const int warp = t >> 5, lane = t & 31;
    const int b = blockIdx.z;
    const int off = b * LSTROKES;

    // Issue round-0 param loads FIRST (longest latency chain).
    const int sl0 = off + warp * 64 + lane;
    const float4 mA0 = __ldg(g_matA + sl0);
    const float4 mB0 = __ldg(g_matB + sl0);

    // Per-warp "every brush texel > 0" flag (no block barrier).
    const bool fv = (__ldg(g_blockfull + lane) != 0) &
                    (__ldg(g_blockfull + 32 + lane) != 0);
    const bool allones = __all_sync(0xFFFFFFFFu, fv);

    const int tileX = blockIdx.x * 8;
    const int tileY = blockIdx.y * 4;
    const int w = tileX + (lane & 7);
    const int h = tileY + (lane >> 3);
    const float bx = bgrid(w);
    const float by = bgrid(h);
    const float c64 = 0.015625f;
    const float bxl = bx - ((w > 0)   ? c64 : 0.0f);
    const float bxh = bx + ((w < 127) ? c64 : 0.0f);
    const float byl = by - ((h > 0)   ? c64 : 0.0f);
    const float byh = by + ((h < 127) ? c64 : 0.0f);
    // Expanded rect (tile ∪ erosion ring): center + half-extents.
    const float tx0 = bgrid(max(tileX - 1, 0)), tx1 = bgrid(min(tileX + 8, 127));
    const float ty0 = bgrid(max(tileY - 1, 0)), ty1 = bgrid(min(tileY + 4, 127));
    const float ecx = 0.5f * (tx0 + tx1), ehx = 0.5f * (tx1 - tx0);
    const float ecy = 0.5f * (ty0 + ty1), ehy = 0.5f * (ty1 - ty0);

    int myWin = -1;
    bool done = false;

    #pragma unroll 1
    for (int r = 0; r < 2; ++r) {
        const float4 mA = (r == 0) ? mA0 : __ldg(g_matA + sl0 + 32);
        const float4 mB = (r == 0) ? mB0 : __ldg(g_matB + sl0 + 32);
        const float a = mA.x, bb = mA.y, cc = mA.z, d = mA.w;
        const float e = mB.x, f = mB.y;

        // Interval arithmetic over expanded rect.
        const float gxc = fmaf(ecx, a, fmaf(ecy, bb, cc));
        const float gyc = fmaf(ecx, d, fmaf(ecy, e,  f));
        const float devx = fmaf(fabsf(a), ehx, fabsf(bb) * ehy);
        const float devy = fmaf(fabsf(d), ehx, fabsf(e)  * ehy);
        const float axc = fabsf(gxc), ayc = fabsf(gyc);

        const bool cand = (axc - devx <= 1.002f) & (ayc - devy <= 1.002f);
        const bool full = allones & cand &
                          (axc + devx <= 0.998f) & (ayc + devy <= 0.998f);

        const unsigned candM = __ballot_sync(0xFFFFFFFFu, cand);
        const unsigned fullM = __ballot_sync(0xFFFFFFFFu, full);

        int fullLane = -1;
        unsigned procM = candM;
        if (fullM) {
            fullLane = __ffs(fullM) - 1;                 // highest full stroke
            procM = candM & ((1u << fullLane) - 1u);     // only partials above
        }

        // Serial loop over remaining candidates (uniform __ldg reload).
        int iter = 0;
        while (procM) {
            const int bit = __ffs(procM) - 1;            // highest stroke first
            procM &= procM - 1;
            const int su = off + warp * 64 + r * 32 + bit;   // uniform address
            const float4 uA = __ldg(g_matA + su);
            const float4 uB = __ldg(g_matB + su);
            const float w00 = uA.x, w01 = uA.y, w02 = uA.z;
            const float w10 = uA.w, w11 = uB.x, w12 = uB.y;
            const int l = (63 - (r * 32 + bit)) * 4 + warp;  // true stroke id

            if (allones) {
                // Center-first early reject (center ∈ 9-stencil; corners valid
                // ⇒ all 9 valid, so failing center ⇒ reject without corners).
                bool ok = !done &&
                          valid_fast(bx, by, w00, w01, w02, w10, w11, w12);
                if (__any_sync(0xFFFFFFFFu, ok)) {
                    if (ok) {
                        ok = valid_fast(bxl, byl, w00, w01, w02, w10, w11, w12) &
                             valid_fast(bxl, byh, w00, w01, w02, w10, w11, w12) &
                             valid_fast(bxh, byl, w00, w01, w02, w10, w11, w12) &
                             valid_fast(bxh, byh, w00, w01, w02, w10, w11, w12);
                        if (ok) { myWin = l; done = true; }
                    }
                }
            } else if (!done) {
                const int idx = (uB.z != 0.0f) ? 1 : 0;
                const float gx = fmaf(bx, w00, fmaf(by, w01, w02));
                const float gy = fmaf(bx, w10, fmaf(by, w11, w12));
                if (alpha_slow(idx, gx, gy)) {
                    bool ok = true;
                    #pragma unroll
                    for (int k = 0; k < 9; ++k) {
                        const int dh = k / 3 - 1, dw = k % 3 - 1;
                        if (dh == 0 && dw == 0) continue;
                        if ((unsigned)(h + dh) >= 128u) continue;
                        if ((unsigned)(w + dw) >= 128u) continue;
                        const float bxn = bx + (float)dw * c64;
                        const float byn = by + (float)dh * c64;
                        const float gxn = fmaf(bxn, w00, fmaf(byn, w01, w02));
                        const float gyn = fmaf(bxn, w10, fmaf(byn, w11, w12));
                        ok &= alpha_slow(idx, gxn, gyn);
                    }
                    if (ok) { myWin = l; done = true; }
                }
            }
            if ((++iter & 7) == 0 && __all_sync(0xFFFFFFFFu, done)) break;
        }

        // Resolve still-open lanes to the highest full-cover stroke.
        if (fullLane >= 0 && !done) {
            myWin = (63 - (r * 32 + fullLane)) * 4 + warp;
            done = true;
        }
        if (__all_sync(0xFFFFFFFFu, done)) break;
    }

    s_win[warp][lane] = myWin;
    __syncthreads();

    // Warp 0: combine deck winners by max, bilinear-sample, write.
    if (warp == 0) {
        const int wn = max(max(s_win[0][lane], s_win[1][lane]),
                           max(s_win[2][lane], s_win[3][lane]));
        float oR = 0.0f, oG = 0.0f, oB = 0.0f;
        if (wn >= 0) {
            const int gl = off + deck_pidx(wn);          // permuted lookup
            const float4 mA = __ldg(g_matA + gl);
            const float4 mB = __ldg(g_matB + gl);
            const float4 cl = __ldg(g_col  + gl);
            const int idx = (mB.z != 0.0f) ? 1 : 0;
            const float gx = fmaf(bx, mA.x, fmaf(by, mA.y, mA.z));
            const float gy = fmaf(bx, mA.w, fmaf(by, mB.x, mB.y));
            const float* im = brushes + (size_t)idx * (BR * BR);
            const float x = ((gx + 1.0f) * 512.0f - 1.0f) * 0.5f;
            const float y = ((gy + 1.0f) * 512.0f - 1.0f) * 0.5f;
            const float xf = floorf(x), yf = floorf(y);
            const int x0i = (int)xf, y0i = (int)yf;
            const float wx1 = x - xf, wx0 = 1.0f - wx1;
            const float wy1 = y - yf, wy0 = 1.0f - wy1;
            const float sV =
                tap(im, x0i,     y0i)     * (wx0 * wy0) +
                tap(im, x0i + 1, y0i)     * (wx1 * wy0) +
                tap(im, x0i,     y0i + 1) * (wx0 * wy1) +
                tap(im, x0i + 1, y0i + 1) * (wx1 * wy1);
            oR = sV * cl.x;
            oG = sV * cl.y;
            oB = sV * cl.z;
        }
        const int outb = ((b * 3) * IMG + h) * IMG + w;
        out[outb]                 = oR;
        out[outb + IMG * IMG]     = oG;
        out[outb + 2 * IMG * IMG] = oB;
    }
}

// ---------------------------------------------------------------------------
extern "C" void kernel_launch(void* const* d_in, const int* in_sizes, int n_in,
                              void* d_out, int out_size) {
    const float* params  = (const float*)d_in[0];   // (4,256,8)
    const float* brushes = (const float*)d_in[1];   // (2,1,512,512)
    float* out = (float*)d_out;                     // (4,3,128,128)

    (void)in_sizes; (void)n_in; (void)out_size;

    prep_and_mask_kernel<<<96, 256>>>(params, brushes);

    dim3 grid(IMG / 8, IMG / 4, 4);                 // 2048 blocks x 128 threads
    render_kernel<<<grid, 128>>>(brushes, out);
}

// round 12
// speedup vs baseline: 1.0175x; 1.0175x over previous
#include <cuda_runtime.h>
#include <cstdint>

#define IMG 128
#define BR  512
#define NSTROKES 1024
#define LSTROKES 256

// Scratch (device-global; no mallocs allowed).
__device__ uint32_t g_mask[2 * (BR * BR / 32)];   // fine brush>0 mask (fallback)
__device__ uint32_t g_coarse[512];                // 1 bit per fine word == all-ones
__device__ int      g_blockfull[64];              // per-prep-block "all ones" flag
// Packed SoA stroke params in DECK-MAJOR PERMUTED order:
//   stroke m (0..255 within batch) stored at pidx = (m&3)*64 + (63 - m/4)
__device__ float4 g_matA[NSTROKES];               // w00,w01,w02,w10
__device__ float4 g_matB[NSTROKES];               // w11,w12,bidx,0
__device__ float4 g_col[NSTROKES];                // cr,cg,cb,0

__device__ __forceinline__ int deck_pidx(int m) { // m = stroke index within batch
    return (m & 3) * 64 + (63 - (m >> 2));
}

// ---------------------------------------------------------------------------
// Kernel 1 (fused): blocks [0,64) build fine mask + coarse summary + block
// all-ones flag; blocks [64,96) compute stroke warp matrices (fp64 sin/cos
// spread over 32 SMs) and store them deck-major permuted.
// ---------------------------------------------------------------------------
__global__ void prep_and_mask_kernel(const float* __restrict__ params,
                                     const float* __restrict__ brushes) {
    const int bid = blockIdx.x;
    const int t = threadIdx.x;

    if (bid < 64) {
        __shared__ uint32_t s_f[8];
        const int word = bid * 256 + t;                 // 0 .. 16383
        const float4* src = (const float4*)brushes + word * 8;
        uint32_t m = 0;
        #pragma unroll
        for (int j = 0; j < 8; ++j) {
            float4 v = src[j];
            m |= ((v.x > 0.0f) ? 1u : 0u) << (4 * j + 0);
            m |= ((v.y > 0.0f) ? 1u : 0u) << (4 * j + 1);
            m |= ((v.z > 0.0f) ? 1u : 0u) << (4 * j + 2);
            m |= ((v.w > 0.0f) ? 1u : 0u) << (4 * j + 3);
        }
        g_mask[word] = m;
        unsigned full = __ballot_sync(0xFFFFFFFFu, m == 0xFFFFFFFFu);
        if ((t & 31) == 0) { g_coarse[word >> 5] = full; s_f[t >> 5] = full; }
        __syncthreads();
        if (t == 0) {
            bool all = true;
            #pragma unroll
            for (int i = 0; i < 8; ++i) all &= (s_f[i] == 0xFFFFFFFFu);
            g_blockfull[bid] = all ? 1 : 0;
        }
    } else {
        if (t >= 32) return;
        const int n = (bid - 64) * 32 + t;              // 0 .. 1023
        const float* p = params + n * 8;
        float x0 = p[0], y0 = p[1], w = p[2], h = p[3], th = p[4];

        // JAX: sin(fl32(pi)*theta), f32 product; correctly-rounded double
        // sin/cos keeps binary-alpha decisions bit-stable vs reference.
        float prod = 3.14159274101257324219f * th;
        float s = (float)sin((double)prod);
        float c = (float)cos((double)prod);

        float tx = 1.0f - 2.0f * x0;
        float ty = 1.0f - 2.0f * y0;
        const float w00 = c / w;
        const float w01 = s / w;
        const float w02 = (tx * c) / w + (ty * s) / w;
        const float w10 = -(s / h);
        const float w11 = c / h;
        const float w12 = (ty * c) / h - (tx * s) / h;

        const int b = n >> 8;                            // batch
        const int m = n & 255;                           // stroke within batch
        const int pidx = b * 256 + deck_pidx(m);
        g_matA[pidx] = make_float4(w00, w01, w02, w10);
        g_matB[pidx] = make_float4(w11, w12, (h > w) ? 0.0f : 1.0f, 0.0f);
        g_col[pidx]  = make_float4(p[5], p[6], p[7], 0.0f);
    }
}

// ---------------------------------------------------------------------------
// Render helpers (EXACT formulas — must match reference bit-for-bit).
// ---------------------------------------------------------------------------
__device__ __forceinline__ bool alpha_slow(int brush, float gx, float gy) {
    float x = ((gx + 1.0f) * 512.0f - 1.0f) * 0.5f;
    float y = ((gy + 1.0f) * 512.0f - 1.0f) * 0.5f;
    int ix = __float2int_rn(x);
    int iy = __float2int_rn(y);
    if ((unsigned)ix >= 512u || (unsigned)iy >= 512u) return false;
    int wi = (brush << 13) + (iy << 4) + (ix >> 5);
    if ((__ldg(g_coarse + (wi >> 5)) >> (wi & 31)) & 1u) return true;
    return (__ldg(g_mask + wi) >> (ix & 31)) & 1u;
}

__device__ __forceinline__ bool valid_fast(float bxn, float byn,
                                           float w00, float w01, float w02,
                                           float w10, float w11, float w12) {
    const float gx = fmaf(bxn, w00, fmaf(byn, w01, w02));
    const float gy = fmaf(bxn, w10, fmaf(byn, w11, w12));
    const float x = ((gx + 1.0f) * 512.0f - 1.0f) * 0.5f;
    const float y = ((gy + 1.0f) * 512.0f - 1.0f) * 0.5f;
    const int ix = __float2int_rn(x);
    const int iy = __float2int_rn(y);
    return ((unsigned)ix < 512u) & ((unsigned)iy < 512u);
}

__device__ __forceinline__ float tap(const float* __restrict__ im, int ix, int iy) {
    bool valid = ((unsigned)ix < 512u) && ((unsigned)iy < 512u);
    int cx = min(max(ix, 0), 511);
    int cy = min(max(iy, 0), 511);
    float v = __ldg(im + cy * 512 + cx);
    return valid ? v : 0.0f;
}

__device__ __forceinline__ float bgrid(int i) {     // exact base-grid coord
    return (2.0f * (float)i + 1.0f) * (1.0f / 128.0f) - 1.0f;
}

// ---------------------------------------------------------------------------
// Render: 2048 blocks x 128 threads = 1 (batch,tile); warp k owns strokes
// l ≡ k (mod 4) descending (coalesced LDG.128). After its scan each lane
// SPECULATIVELY computes its deck-winner's bilinear RGB (off critical path);
// the finale is pure smem argmax + store (no dependent global loads).
// ---------------------------------------------------------------------------
__global__ __launch_bounds__(128, 10)
void render_kernel(const float* __restrict__ brushes, float* __restrict__ out) {
    __shared__ int   s_win[4][32];
    __shared__ float s_R[4][32], s_G[4][32], s_B[4][32];

    const int t = threadIdx.x;
    const int warp = t >> 5, lane = t & 31;
    const int b = blockIdx.z;
    const int off = b * LSTROKES;

    // Issue round-0 param loads FIRST (longest latency chain).
    const int sl0 = off + warp * 64 + lane;
    const float4 mA0 = __ldg(g_matA + sl0);
    const float4 mB0 = __ldg(g_matB + sl0);

    // Per-warp "every brush texel > 0" flag (no block barrier).
    const bool fv = (__ldg(g_blockfull + lane) != 0) &
                    (__ldg(g_blockfull + 32 + lane) != 0);
    const bool allones = __all_sync(0xFFFFFFFFu, fv);

    const int tileX = blockIdx.x * 8;
    const int tileY = blockIdx.y * 4;
    const int w = tileX + (lane & 7);
    const int h = tileY + (lane >> 3);
    const float bx = bgrid(w);
    const float by = bgrid(h);
    const float c64 = 0.015625f;
    const float bxl = bx - ((w > 0)   ? c64 : 0.0f);
    const float bxh = bx + ((w < 127) ? c64 : 0.0f);
    const float byl = by - ((h > 0)   ? c64 : 0.0f);
    const float byh = by + ((h < 127) ? c64 : 0.0f);
    // Expanded rect (tile ∪ erosion ring): center + half-extents.
    const float tx0 = bgrid(max(tileX - 1, 0)), tx1 = bgrid(min(tileX + 8, 127));
    const float ty0 = bgrid(max(tileY - 1, 0)), ty1 = bgrid(min(tileY + 4, 127));
    const float ecx = 0.5f * (tx0 + tx1), ehx = 0.5f * (tx1 - tx0);
    const float ecy = 0.5f * (ty0 + ty1), ehy = 0.5f * (ty1 - ty0);

    int myWin = -1;
    bool done = false;

    #pragma unroll 1
    for (int r = 0; r < 2; ++r) {
        const float4 mA = (r == 0) ? mA0 : __ldg(g_matA + sl0 + 32);
        const float4 mB = (r == 0) ? mB0 : __ldg(g_matB + sl0 + 32);
        const float a = mA.x, bb = mA.y, cc = mA.z, d = mA.w;
        const float e = mB.x, f = mB.y;

        // Interval arithmetic over expanded rect.
        const float gxc = fmaf(ecx, a, fmaf(ecy, bb, cc));
        const float gyc = fmaf(ecx, d, fmaf(ecy, e,  f));
        const float devx = fmaf(fabsf(a), ehx, fabsf(bb) * ehy);
        const float devy = fmaf(fabsf(d), ehx, fabsf(e)  * ehy);
        const float axc = fabsf(gxc), ayc = fabsf(gyc);

        const bool cand = (axc - devx <= 1.002f) & (ayc - devy <= 1.002f);
        const bool full = allones & cand &
                          (axc + devx <= 0.998f) & (ayc + devy <= 0.998f);

        const unsigned candM = __ballot_sync(0xFFFFFFFFu, cand);
        const unsigned fullM = __ballot_sync(0xFFFFFFFFu, full);

        int fullLane = -1;
        unsigned procM = candM;
        if (fullM) {
            fullLane = __ffs(fullM) - 1;                 // highest full stroke
            procM = candM & ((1u << fullLane) - 1u);     // only partials above
        }

        // Serial loop over remaining candidates (uniform __ldg reload).
        int iter = 0;
        while (procM) {
            const int bit = __ffs(procM) - 1;            // highest stroke first
            procM &= procM - 1;
            const int su = off + warp * 64 + r * 32 + bit;   // uniform address
            const float4 uA = __ldg(g_matA + su);
            const float4 uB = __ldg(g_matB + su);
            const float w00 = uA.x, w01 = uA.y, w02 = uA.z;
            const float w10 = uA.w, w11 = uB.x, w12 = uB.y;
            const int l = (63 - (r * 32 + bit)) * 4 + warp;  // true stroke id

            if (allones) {
                // Center-first early reject (center ∈ 9-stencil; all-corners
                // valid ⇒ all 9 valid; failing center ⇒ reject early).
                bool ok = !done &&
                          valid_fast(bx, by, w00, w01, w02, w10, w11, w12);
                if (__any_sync(0xFFFFFFFFu, ok)) {
                    if (ok) {
                        ok = valid_fast(bxl, byl, w00, w01, w02, w10, w11, w12) &
                             valid_fast(bxl, byh, w00, w01, w02, w10, w11, w12) &
                             valid_fast(bxh, byl, w00, w01, w02, w10, w11, w12) &
                             valid_fast(bxh, byh, w00, w01, w02, w10, w11, w12);
                        if (ok) { myWin = l; done = true; }
                    }
                }
            } else if (!done) {
                const int idx = (uB.z != 0.0f) ? 1 : 0;
                const float gx = fmaf(bx, w00, fmaf(by, w01, w02));
                const float gy = fmaf(bx, w10, fmaf(by, w11, w12));
                if (alpha_slow(idx, gx, gy)) {
                    bool ok = true;
                    #pragma unroll
                    for (int k = 0; k < 9; ++k) {
                        const int dh = k / 3 - 1, dw = k % 3 - 1;
                        if (dh == 0 && dw == 0) continue;
                        if ((unsigned)(h + dh) >= 128u) continue;
                        if ((unsigned)(w + dw) >= 128u) continue;
                        const float bxn = bx + (float)dw * c64;
                        const float byn = by + (float)dh * c64;
                        const float gxn = fmaf(bxn, w00, fmaf(byn, w01, w02));
                        const float gyn = fmaf(bxn, w10, fmaf(byn, w11, w12));
                        ok &= alpha_slow(idx, gxn, gyn);
                    }
                    if (ok) { myWin = l; done = true; }
                }
            }
            if ((++iter & 7) == 0 && __all_sync(0xFFFFFFFFu, done)) break;
        }

        // Resolve still-open lanes to the highest full-cover stroke.
        if (fullLane >= 0 && !done) {
            myWin = (63 - (r * 32 + fullLane)) * 4 + warp;
            done = true;
        }
        if (__all_sync(0xFFFFFFFFu, done)) break;
    }

    // Speculative per-deck sample: compute this lane's deck-winner RGB now,
    // in parallel across all 4 warps (keeps the post-barrier path load-free).
    float oR = 0.0f, oG = 0.0f, oB = 0.0f;
    if (myWin >= 0) {
        const int gl = off + deck_pidx(myWin);
        const float4 mA = __ldg(g_matA + gl);
        const float4 mB = __ldg(g_matB + gl);
        const float4 cl = __ldg(g_col  + gl);
        const int idx = (mB.z != 0.0f) ? 1 : 0;
        const float gx = fmaf(bx, mA.x, fmaf(by, mA.y, mA.z));
        const float gy = fmaf(bx, mA.w, fmaf(by, mB.x, mB.y));
        const float* im = brushes + (size_t)idx * (BR * BR);
        const float x = ((gx + 1.0f) * 512.0f - 1.0f) * 0.5f;
        const float y = ((gy + 1.0f) * 512.0f - 1.0f) * 0.5f;
        const float xf = floorf(x), yf = floorf(y);
        const int x0i = (int)xf, y0i = (int)yf;
        const float wx1 = x - xf, wx0 = 1.0f - wx1;
        const float wy1 = y - yf, wy0 = 1.0f - wy1;
        const float sV =
            tap(im, x0i,     y0i)     * (wx0 * wy0) +
            tap(im, x0i + 1, y0i)     * (wx1 * wy0) +
            tap(im, x0i,     y0i + 1) * (wx0 * wy1) +
            tap(im, x0i + 1, y0i + 1) * (wx1 * wy1);
        oR = sV * cl.x;
        oG = sV * cl.y;
        oB = sV * cl.z;
    }
    s_win[warp][lane] = myWin;
    s_R[warp][lane] = oR;
    s_G[warp][lane] = oG;
    s_B[warp][lane] = oB;
    __syncthreads();

    // Warp 0: pick deck with max winner index; copy its precomputed RGB.
    if (warp == 0) {
        int bestK = 0;
        int bestW = s_win[0][lane];
        #pragma unroll
        for (int k = 1; k < 4; ++k) {
            const int wk = s_win[k][lane];
            if (wk > bestW) { bestW = wk; bestK = k; }
        }
        const float R = s_R[bestK][lane];
        const float G = s_G[bestK][lane];
        const float B = s_B[bestK][lane];
        const int outb = ((b * 3) * IMG + h) * IMG + w;
        out[outb]                 = R;
        out[outb + IMG * IMG]     = G;
        out[outb + 2 * IMG * IMG] = B;
    }
}

// ---------------------------------------------------------------------------
extern "C" void kernel_launch(void* const* d_in, const int* in_sizes, int n_in,
                              void* d_out, int out_size) {
    const float* params  = (const float*)d_in[0];   // (4,256,8)
    const float* brushes = (const float*)d_in[1];   // (2,1,512,512)
    float* out = (float*)d_out;                     // (4,3,128,128)

    (void)in_sizes; (void)n_in; (void)out_size;

    prep_and_mask_kernel<<<96, 256>>>(params, brushes);

    dim3 grid(IMG / 8, IMG / 4, 4);                 // 2048 blocks x 128 threads
    render_kernel<<<grid, 128>>>(brushes, out);
}

// round 13
// speedup vs baseline: 1.1866x; 1.1662x over previous
#include <cuda_runtime.h>
#include <cstdint>

#define IMG 128
#define BR  512
#define NSTROKES 1024
#define LSTROKES 256

// Scratch (device-global; no mallocs allowed).
__device__ uint32_t g_mask[2 * (BR * BR / 32)];   // fine brush>0 mask (fallback)
__device__ uint32_t g_coarse[512];                // 1 bit per fine word == all-ones
__device__ int      g_blockfull[64];              // per-prep-block "all ones" flag
// Packed SoA stroke params in REVERSED order: stroke m stored at 255 - m
// (per batch), so a warp scanning positions ascending sees strokes descending,
// coalesced.
__device__ float4 g_matA[NSTROKES];               // w00,w01,w02,w10
__device__ float4 g_matB[NSTROKES];               // w11,w12,bidx,0
__device__ float4 g_col[NSTROKES];                // cr,cg,cb,0

// ---------------------------------------------------------------------------
// Kernel 1 (fused): blocks [0,64) compute stroke warp matrices — fp64 sin/cos
// split across thread PAIRS (even=cos, odd=sin, shfl exchange) => half the
// exposed fp64 chain, 64 SMs. Blocks [64,128) build fine mask + coarse
// summary + block all-ones flags.
// ---------------------------------------------------------------------------
__global__ void prep_and_mask_kernel(const float* __restrict__ params,
                                     const float* __restrict__ brushes) {
    const int bid = blockIdx.x;
    const int t = threadIdx.x;

    if (bid < 64) {
        if (t >= 32) return;
        const int n = bid * 16 + (t >> 1);              // stroke 0..1023
        const float* p = params + n * 8;
        const float x0 = p[0], y0 = p[1], w = p[2], h = p[3], th = p[4];

        // JAX: sin(fl32(pi)*theta), f32 product; correctly-rounded double
        // sin/cos keeps binary-alpha decisions bit-stable vs reference.
        const float prod = 3.14159274101257324219f * th;
        const float mine = (t & 1) ? (float)sin((double)prod)
                                   : (float)cos((double)prod);
        const float other = __shfl_xor_sync(0xFFFFFFFFu, mine, 1);
        if ((t & 1) == 0) {
            const float c = mine, s = other;
            const float tx = 1.0f - 2.0f * x0;
            const float ty = 1.0f - 2.0f * y0;
            const float w00 = c / w;
            const float w01 = s / w;
            const float w02 = (tx * c) / w + (ty * s) / w;
            const float w10 = -(s / h);
            const float w11 = c / h;
            const float w12 = (ty * c) / h - (tx * s) / h;

            const int b = n >> 8;                        // batch
            const int m = n & 255;                       // stroke within batch
            const int pidx = b * 256 + (255 - m);        // reversed
            g_matA[pidx] = make_float4(w00, w01, w02, w10);
            g_matB[pidx] = make_float4(w11, w12, (h > w) ? 0.0f : 1.0f, 0.0f);
            g_col[pidx]  = make_float4(p[5], p[6], p[7], 0.0f);
        }
    } else {
        __shared__ uint32_t s_f[8];
        const int mb = bid - 64;
        const int word = mb * 256 + t;                  // 0 .. 16383
        const float4* src = (const float4*)brushes + word * 8;
        uint32_t m = 0;
        #pragma unroll
        for (int j = 0; j < 8; ++j) {
            float4 v = src[j];
            m |= ((v.x > 0.0f) ? 1u : 0u) << (4 * j + 0);
            m |= ((v.y > 0.0f) ? 1u : 0u) << (4 * j + 1);
            m |= ((v.z > 0.0f) ? 1u : 0u) << (4 * j + 2);
            m |= ((v.w > 0.0f) ? 1u : 0u) << (4 * j + 3);
        }
        g_mask[word] = m;
        unsigned full = __ballot_sync(0xFFFFFFFFu, m == 0xFFFFFFFFu);
        if ((t & 31) == 0) { g_coarse[word >> 5] = full; s_f[t >> 5] = full; }
        __syncthreads();
        if (t == 0) {
            bool all = true;
            #pragma unroll
            for (int i = 0; i < 8; ++i) all &= (s_f[i] == 0xFFFFFFFFu);
            g_blockfull[mb] = all ? 1 : 0;
        }
    }
}

// ---------------------------------------------------------------------------
// Render helpers (EXACT formulas — must match reference bit-for-bit).
// ---------------------------------------------------------------------------
__device__ __forceinline__ bool alpha_slow(int brush, float gx, float gy) {
    float x = ((gx + 1.0f) * 512.0f - 1.0f) * 0.5f;
    float y = ((gy + 1.0f) * 512.0f - 1.0f) * 0.5f;
    int ix = __float2int_rn(x);
    int iy = __float2int_rn(y);
    if ((unsigned)ix >= 512u || (unsigned)iy >= 512u) return false;
    int wi = (brush << 13) + (iy << 4) + (ix >> 5);
    if ((__ldg(g_coarse + (wi >> 5)) >> (wi & 31)) & 1u) return true;
    return (__ldg(g_mask + wi) >> (ix & 31)) & 1u;
}

__device__ __forceinline__ bool valid_fast(float bxn, float byn,
                                           float w00, float w01, float w02,
                                           float w10, float w11, float w12) {
    const float gx = fmaf(bxn, w00, fmaf(byn, w01, w02));
    const float gy = fmaf(bxn, w10, fmaf(byn, w11, w12));
    const float x = ((gx + 1.0f) * 512.0f - 1.0f) * 0.5f;
    const float y = ((gy + 1.0f) * 512.0f - 1.0f) * 0.5f;
    const int ix = __float2int_rn(x);
    const int iy = __float2int_rn(y);
    return ((unsigned)ix < 512u) & ((unsigned)iy < 512u);
}

__device__ __forceinline__ float tap(const float* __restrict__ im, int ix, int iy) {
    bool valid = ((unsigned)ix < 512u) && ((unsigned)iy < 512u);
    int cx = min(max(ix, 0), 511);
    int cy = min(max(iy, 0), 511);
    float v = __ldg(im + cy * 512 + cx);
    return valid ? v : 0.0f;
}

__device__ __forceinline__ float bgrid(int i) {     // exact base-grid coord
    return (2.0f * (float)i + 1.0f) * (1.0f / 128.0f) - 1.0f;
}

// ---------------------------------------------------------------------------
// Render: ONE WARP per 8x4 tile (2048 warps = 512 blocks x 4 independent
// warps; no smem, no block barriers). Strokes scanned in TRUE descending
// order, 32/round, software-pipelined param loads; fullM prune gives early
// exit typically after round 0.
// ---------------------------------------------------------------------------
__global__ __launch_bounds__(128, 10)
void render_kernel(const float* __restrict__ brushes, float* __restrict__ out) {
    const int t = threadIdx.x;
    const int warp = t >> 5, lane = t & 31;
    const int b = blockIdx.z;
    const int off = b * LSTROKES;

    // Warp's tile.
    const int wt = blockIdx.x * 4 + warp;               // 0..511
    const int tileX = (wt & 15) * 8;
    const int tileY = (wt >> 4) * 4;

    // Prefetch round-0 params immediately.
    const int base0 = off + lane;
    float4 nA = __ldg(g_matA + base0);
    float4 nB = __ldg(g_matB + base0);

    // Per-warp "every brush texel > 0" flag.
    const bool fv = (__ldg(g_blockfull + lane) != 0) &
                    (__ldg(g_blockfull + 32 + lane) != 0);
    const bool allones = __all_sync(0xFFFFFFFFu, fv);

    const int w = tileX + (lane & 7);
    const int h = tileY + (lane >> 3);
    const float bx = bgrid(w);
    const float by = bgrid(h);
    const float c64 = 0.015625f;
    const float bxl = bx - ((w > 0)   ? c64 : 0.0f);
    const float bxh = bx + ((w < 127) ? c64 : 0.0f);
    const float byl = by - ((h > 0)   ? c64 : 0.0f);
    const float byh = by + ((h < 127) ? c64 : 0.0f);
    // Expanded rect (tile ∪ erosion ring): center + half-extents.
    const float tx0 = bgrid(max(tileX - 1, 0)), tx1 = bgrid(min(tileX + 8, 127));
    const float ty0 = bgrid(max(tileY - 1, 0)), ty1 = bgrid(min(tileY + 4, 127));
    const float ecx = 0.5f * (tx0 + tx1), ehx = 0.5f * (tx1 - tx0);
    const float ecy = 0.5f * (ty0 + ty1), ehy = 0.5f * (ty1 - ty0);

    int myPos = -1;            // position in reversed array (lower = later stroke)
    bool done = false;

    #pragma unroll 1
    for (int r = 0; r < 8; ++r) {
        const float4 mA = nA;
        const float4 mB = nB;
        // Prefetch next round while this one is processed.
        if (r < 7) {
            nA = __ldg(g_matA + base0 + (r + 1) * 32);
            nB = __ldg(g_matB + base0 + (r + 1) * 32);
        }
        const float a = mA.x, bb = mA.y, cc = mA.z, d = mA.w;
        const float e = mB.x, f = mB.y;

        // Interval arithmetic over expanded rect.
        const float gxc = fmaf(ecx, a, fmaf(ecy, bb, cc));
        const float gyc = fmaf(ecx, d, fmaf(ecy, e,  f));
        const float devx = fmaf(fabsf(a), ehx, fabsf(bb) * ehy);
        const float devy = fmaf(fabsf(d), ehx, fabsf(e)  * ehy);
        const float axc = fabsf(gxc), ayc = fabsf(gyc);

        const bool cand = (axc - devx <= 1.002f) & (ayc - devy <= 1.002f);
        const bool full = allones & cand &
                          (axc + devx <= 0.998f) & (ayc + devy <= 0.998f);

        const unsigned candM = __ballot_sync(0xFFFFFFFFu, cand);
        const unsigned fullM = __ballot_sync(0xFFFFFFFFu, full);

        int fullLane = -1;
        unsigned procM = candM;
        if (fullM) {
            fullLane = __ffs(fullM) - 1;                 // highest full stroke
            procM = candM & ((1u << fullLane) - 1u);     // only partials above
        }

        // Serial loop over remaining candidates (uniform __ldg reload).
        int iter = 0;
        while (procM) {
            const int bit = __ffs(procM) - 1;            // highest stroke first
            procM &= procM - 1;
            const int su = off + r * 32 + bit;           // uniform address
            const float4 uA = __ldg(g_matA + su);
            const float4 uB = __ldg(g_matB + su);
            const float w00 = uA.x, w01 = uA.y, w02 = uA.z;
            const float w10 = uA.w, w11 = uB.x, w12 = uB.y;

            if (allones) {
                // Center-first early reject; exact 4-corner accept.
                bool ok = !done &&
                          valid_fast(bx, by, w00, w01, w02, w10, w11, w12);
                if (__any_sync(0xFFFFFFFFu, ok)) {
                    if (ok) {
                        ok = valid_fast(bxl, byl, w00, w01, w02, w10, w11, w12) &
                             valid_fast(bxl, byh, w00, w01, w02, w10, w11, w12) &
                             valid_fast(bxh, byl, w00, w01, w02, w10, w11, w12) &
                             valid_fast(bxh, byh, w00, w01, w02, w10, w11, w12);
                        if (ok) { myPos = r * 32 + bit; done = true; }
                    }
                }
            } else if (!done) {
                const int idx = (uB.z != 0.0f) ? 1 : 0;
                const float gx = fmaf(bx, w00, fmaf(by, w01, w02));
                const float gy = fmaf(bx, w10, fmaf(by, w11, w12));
                if (alpha_slow(idx, gx, gy)) {
                    bool ok = true;
                    #pragma unroll
                    for (int k = 0; k < 9; ++k) {
                        const int dh = k / 3 - 1, dw = k % 3 - 1;
                        if (dh == 0 && dw == 0) continue;
                        if ((unsigned)(h + dh) >= 128u) continue;
                        if ((unsigned)(w + dw) >= 128u) continue;
                        const float bxn = bx + (float)dw * c64;
                        const float byn = by + (float)dh * c64;
                        const float gxn = fmaf(bxn, w00, fmaf(byn, w01, w02));
                        const float gyn = fmaf(bxn, w10, fmaf(byn, w11, w12));
                        ok &= alpha_slow(idx, gxn, gyn);
                    }
                    if (ok) { myPos = r * 32 + bit; done = true; }
                }
            }
            if ((++iter & 3) == 0 && __all_sync(0xFFFFFFFFu, done)) break;
        }

        // Resolve still-open lanes to the highest full-cover stroke.
        if (fullLane >= 0 && !done) {
            myPos = r * 32 + fullLane;
            done = true;
        }
        if (__all_sync(0xFFFFFFFFu, done)) break;
    }

    // Per-lane finale: sample own winner (first-found == highest stroke).
    float oR = 0.0f, oG = 0.0f, oB = 0.0f;
    if (myPos >= 0) {
        const int gl = off + myPos;
        const float4 mA = __ldg(g_matA + gl);
        const float4 mB = __ldg(g_matB + gl);
        const float4 cl = __ldg(g_col  + gl);
        const int idx = (mB.z != 0.0f) ? 1 : 0;
        const float gx = fmaf(bx, mA.x, fmaf(by, mA.y, mA.z));
        const float gy = fmaf(bx, mA.w, fmaf(by, mB.x, mB.y));
        const float* im = brushes + (size_t)idx * (BR * BR);
        const float x = ((gx + 1.0f) * 512.0f - 1.0f) * 0.5f;
        const float y = ((gy + 1.0f) * 512.0f - 1.0f) * 0.5f;
        const float xf = floorf(x), yf = floorf(y);
        const int x0i = (int)xf, y0i = (int)yf;
        const float wx1 = x - xf, wx0 = 1.0f - wx1;
        const float wy1 = y - yf, wy0 = 1.0f - wy1;
        const float sV =
            tap(im, x0i,     y0i)     * (wx0 * wy0) +
            tap(im, x0i + 1, y0i)     * (wx1 * wy0) +
            tap(im, x0i,     y0i + 1) * (wx0 * wy1) +
            tap(im, x0i + 1, y0i + 1) * (wx1 * wy1);
        oR = sV * cl.x;
        oG = sV * cl.y;
        oB = sV * cl.z;
    }
    const int outb = ((b * 3) * IMG + h) * IMG + w;
    out[outb]                 = oR;
    out[outb + IMG * IMG]     = oG;
    out[outb + 2 * IMG * IMG] = oB;
}

// ---------------------------------------------------------------------------
extern "C" void kernel_launch(void* const* d_in, const int* in_sizes, int n_in,
                              void* d_out, int out_size) {
    const float* params  = (const float*)d_in[0];   // (4,256,8)
    const float* brushes = (const float*)d_in[1];   // (2,1,512,512)
    float* out = (float*)d_out;                     // (4,3,128,128)

    (void)in_sizes; (void)n_in; (void)out_size;

    prep_and_mask_kernel<<<128, 256>>>(params, brushes);

    dim3 grid(128, 1, 4);                           // 512 blocks x 4 warp-tiles
    render_kernel<<<grid, 128>>>(brushes, out);
}